// round 1
// baseline (speedup 1.0000x reference)
#include <cuda_runtime.h>

#define B_TOT   4096
#define T_TOT   512
#define NF      16
#define NG      12      // 3 gates * H(=4)
#define NH      4
#define BPB     32      // batches per block
#define CH      4       // timesteps per chunk
#define NCHUNK  (T_TOT / CH)        // 128
#define XSTRIDE 20      // padded floats per (b,t) x-row (16 data + 4 pad; 16B-aligned, bank-safe)
#define PROD_T  224     // producer threads (warps 0..6); warp 7 = consumer

__device__ __forceinline__ float sigm_f(float v) {
    // 1/(1+exp(-v)) via MUFU.EX2 + MUFU.RCP (rel err ~2^-21; args are O(1) here)
    float e = __expf(-v);
    return __fdividef(1.0f, 1.0f + e);
}
__device__ __forceinline__ float tanh_f(float v) {
    // (e^{2v}-1)/(e^{2v}+1); |v| <~ 1.5 in this problem, no overflow concerns
    float e = __expf(2.0f * v);
    return __fdividef(e - 1.0f, e + 1.0f);
}

__device__ __forceinline__ void block_bar() {
    asm volatile("bar.sync 0, 256;" ::: "memory");
}

__global__ void __launch_bounds__(256, 1)
gru_fused_kernel(const float* __restrict__ x,
                 const float* __restrict__ w_ih,
                 const float* __restrict__ w_hh,
                 const float* __restrict__ b_ih,
                 const float* __restrict__ b_hh,
                 const float* __restrict__ fc_w,
                 const float* __restrict__ fc_b,
                 float* __restrict__ out)
{
    // xbuf: staged x tile, layout [buf][ (b*CH + t) * XSTRIDE + f ]
    __shared__ __align__(16) float xbuf[2][BPB * CH * XSTRIDE];     // 20480 B
    // gibuf: input-projection tile, layout [buf][ (t*BPB + b) * NG + g ]
    __shared__ __align__(16) float gibuf[2][CH * BPB * NG];         // 12288 B

    const int tid = threadIdx.x;
    const int b0  = blockIdx.x * BPB;

    if (tid < PROD_T) {
        // ================= PRODUCER =================
        // Hold full w_ih (12x16) + b_ih in registers.
        float w[NG][NF];
        float bi[NG];
        #pragma unroll
        for (int j = 0; j < NG; ++j) {
            #pragma unroll
            for (int k = 0; k < NF; k += 4) {
                float4 v = *(const float4*)(w_ih + j * NF + k);
                w[j][k] = v.x; w[j][k+1] = v.y; w[j][k+2] = v.z; w[j][k+3] = v.w;
            }
            bi[j] = b_ih[j];
        }
        // compute-cell assignment (only tid<128 compute; each owns one (b,t) cell)
        const int ct = tid & 3;        // t within chunk
        const int cb = tid >> 2;       // b within block

        for (int it = 0; it < NCHUNK + 2; ++it) {
            // ---- stage x for chunk `it` (coalesced LDG -> SMEM) ----
            if (it < NCHUNK) {
                float* xb = xbuf[it & 1];
                #pragma unroll
                for (int j = 0; j < 3; ++j) {
                    int kq = tid + j * PROD_T;          // quad index 0..511
                    if (kq < BPB * CH * 4) {
                        int q = kq & 3;
                        int t = (kq >> 2) & 3;
                        int b = kq >> 4;
                        const float* src = x + ((size_t)(b0 + b) * T_TOT + (size_t)it * CH + t) * NF + q * 4;
                        float4 v = *(const float4*)src;
                        *(float4*)(xb + (b * CH + t) * XSTRIDE + q * 4) = v;
                    }
                }
            }
            // ---- compute gi for chunk it-1 ----
            int c = it - 1;
            if (c >= 0 && c < NCHUNK && tid < BPB * CH) {
                const float* xb = xbuf[c & 1] + (cb * CH + ct) * XSTRIDE;
                float acc[NG];
                #pragma unroll
                for (int j = 0; j < NG; ++j) acc[j] = bi[j];
                #pragma unroll
                for (int q = 0; q < 4; ++q) {
                    float4 v = *(const float4*)(xb + q * 4);
                    float xv0 = v.x, xv1 = v.y, xv2 = v.z, xv3 = v.w;
                    #pragma unroll
                    for (int j = 0; j < NG; ++j) {
                        acc[j] = fmaf(xv0, w[j][q*4+0], acc[j]);
                        acc[j] = fmaf(xv1, w[j][q*4+1], acc[j]);
                        acc[j] = fmaf(xv2, w[j][q*4+2], acc[j]);
                        acc[j] = fmaf(xv3, w[j][q*4+3], acc[j]);
                    }
                }
                float* gb = gibuf[c & 1] + (ct * BPB + cb) * NG;
                #pragma unroll
                for (int g = 0; g < NG; g += 4) {
                    *(float4*)(gb + g) = make_float4(acc[g], acc[g+1], acc[g+2], acc[g+3]);
                }
            }
            block_bar();
        }
        // producers done (no output)
    } else {
        // ================= CONSUMER (warp 7, one batch per lane) =================
        const int lane = tid & 31;
        float whh[NG][NH];
        float bh[NG];
        #pragma unroll
        for (int j = 0; j < NG; ++j) {
            float4 v = *(const float4*)(w_hh + j * NH);
            whh[j][0] = v.x; whh[j][1] = v.y; whh[j][2] = v.z; whh[j][3] = v.w;
            bh[j] = b_hh[j];
        }
        float fw0 = fc_w[0], fw1 = fc_w[1], fw2 = fc_w[2], fw3 = fc_w[3];
        float fb  = fc_b[0];

        float h[NH] = {0.f, 0.f, 0.f, 0.f};

        for (int it = 0; it < NCHUNK + 2; ++it) {
            int c = it - 2;
            if (c >= 0) {
                const float* gb = gibuf[c & 1];
                #pragma unroll
                for (int s = 0; s < CH; ++s) {
                    const float* g = gb + (s * BPB + lane) * NG;
                    float4 gr4 = *(const float4*)(g);
                    float4 gz4 = *(const float4*)(g + 4);
                    float4 gn4 = *(const float4*)(g + 8);
                    float gi_r[4] = {gr4.x, gr4.y, gr4.z, gr4.w};
                    float gi_z[4] = {gz4.x, gz4.y, gz4.z, gz4.w};
                    float gi_n[4] = {gn4.x, gn4.y, gn4.z, gn4.w};
                    float nh[NH];
                    #pragma unroll
                    for (int j = 0; j < NH; ++j) {
                        float ghr = fmaf(whh[j][3], h[3],
                                    fmaf(whh[j][2], h[2],
                                    fmaf(whh[j][1], h[1],
                                    fmaf(whh[j][0], h[0], bh[j]))));
                        float ghz = fmaf(whh[4+j][3], h[3],
                                    fmaf(whh[4+j][2], h[2],
                                    fmaf(whh[4+j][1], h[1],
                                    fmaf(whh[4+j][0], h[0], bh[4+j]))));
                        float ghn = fmaf(whh[8+j][3], h[3],
                                    fmaf(whh[8+j][2], h[2],
                                    fmaf(whh[8+j][1], h[1],
                                    fmaf(whh[8+j][0], h[0], bh[8+j]))));
                        float r = sigm_f(gi_r[j] + ghr);
                        float z = sigm_f(gi_z[j] + ghz);
                        float n = tanh_f(fmaf(r, ghn, gi_n[j]));
                        nh[j] = fmaf(z, h[j] - n, n);
                    }
                    h[0] = nh[0]; h[1] = nh[1]; h[2] = nh[2]; h[3] = nh[3];
                }
            }
            block_bar();
        }
        float o = fmaf(h[3], fw3, fmaf(h[2], fw2, fmaf(h[1], fw1, fmaf(h[0], fw0, fb))));
        out[b0 + lane] = o;
    }
}

extern "C" void kernel_launch(void* const* d_in, const int* in_sizes, int n_in,
                              void* d_out, int out_size)
{
    const float* x    = (const float*)d_in[0];
    const float* w_ih = (const float*)d_in[1];
    const float* w_hh = (const float*)d_in[2];
    const float* b_ih = (const float*)d_in[3];
    const float* b_hh = (const float*)d_in[4];
    const float* fc_w = (const float*)d_in[5];
    const float* fc_b = (const float*)d_in[6];
    float* out = (float*)d_out;

    gru_fused_kernel<<<B_TOT / BPB, 256>>>(x, w_ih, w_hh, b_ih, b_hh, fc_w, fc_b, out);
}